// round 12
// baseline (speedup 1.0000x reference)
#include <cuda_runtime.h>

// CRF loss: logZ - gold.  T=512, B=512, N=64.
// Exp-space forward. 4 independent chains per 256-thread block. Split
// bar.arrive/bar.sync per chain-step with shadow work in the wait window,
// 4-accumulator matvec, MUFU ex2 precomputed one step ahead, renorm per 6.

#define TT 512
#define BB 512
#define NN 64
#define LOG2E 1.4426950408889634f
#define LN2F  0.6931471805599453f
#define STRIDE_F (BB * NN)

#define FWD_BLOCKS  128                  // 4 chains per 256-thread block
#define GOLD_BLOCKS 1024                 // (T*B)/256
#define TOT_BLOCKS  (FWD_BLOCKS + GOLD_BLOCKS)

typedef unsigned long long ull;

__device__ __align__(16) float g_EpT[NN * NN];   // exp(trans)^T : [j][i]
__device__ double   g_logZ;
__device__ double   g_gold;
__device__ unsigned g_done;

__device__ __forceinline__ float ex2f_(float x) {
    float y; asm("ex2.approx.ftz.f32 %0, %1;" : "=f"(y) : "f"(x)); return y;
}
__device__ __forceinline__ float lg2f_(float x) {
    float y; asm("lg2.approx.ftz.f32 %0, %1;" : "=f"(y) : "f"(x)); return y;
}
__device__ __forceinline__ void fma2_(ull& d, ull a, ull b) {
    asm("fma.rn.f32x2 %0, %1, %2, %0;" : "+l"(d) : "l"(a), "l"(b));
}
__device__ __forceinline__ ull add2_(ull a, ull b) {
    ull d; asm("add.rn.f32x2 %0, %1, %2;" : "=l"(d) : "l"(a), "l"(b));
    return d;
}
__device__ __forceinline__ float pairsum_(ull a) {
    unsigned lo, hi;
    asm("mov.b64 {%0, %1}, %2;" : "=r"(lo), "=r"(hi) : "l"(a));
    return __uint_as_float(lo) + __uint_as_float(hi);
}

// mask dtype: 0=int32, 1=float32, 2=byte  (row t=0 all-true since lengths>=1)
__device__ __forceinline__ int mask_kind(const void* maskp) {
    unsigned w0 = ((const unsigned*)maskp)[0];
    return (w0 == 1u) ? 0 : (w0 == 0x3F800000u ? 1 : 2);
}
__device__ __forceinline__ bool mask_at(const void* maskp, int kind, int idx) {
    if (kind == 0) return ((const int*)maskp)[idx] != 0;
    if (kind == 1) return ((const float*)maskp)[idx] != 0.0f;
    return ((const unsigned char*)maskp)[idx] != 0;
}

// ---------------- init ------------------------------------------------------
__global__ void k_init(const float* __restrict__ trans) {
    int tid = blockIdx.x * blockDim.x + threadIdx.x;
    if (tid < NN * NN) {
        int i = tid & (NN - 1);
        int j = tid >> 6;
        g_EpT[tid] = ex2f_(LOG2E * trans[i * NN + j]);
    }
    if (tid == 0) { g_logZ = 0.0; g_gold = 0.0; g_done = 0u; }
}

// ---------------- fused forward + gold + final ------------------------------
__global__ void __launch_bounds__(256, 1)
k_main(const float* __restrict__ emit,
       const float* __restrict__ trans,
       const float* __restrict__ strans,
       const float* __restrict__ etrans,
       const int*   __restrict__ target,
       const void*  __restrict__ maskp,
       float*       __restrict__ out) {
    __shared__ __align__(16) float pbuf[4][2][NN];  // [chain][buffer][j]
    __shared__ float sslot[4];                      // [chain] raw-sum sample
    __shared__ float red[4][4];                     // [chain] reduce slots

    const int tid = threadIdx.x;

    if (blockIdx.x < FWD_BLOCKS) {
        const int c  = tid >> 6;          // chain 0..3 (warps 2c, 2c+1)
        const int jt = tid & 63;          // state column j within chain
        const int w  = jt >> 5;           // warp-in-chain 0/1
        const int l  = tid & 31;
        const int b  = blockIdx.x * 4 + c;

#define CBAR()     asm volatile("bar.sync %0, %1;"   :: "r"(c + 1), "r"(64)  : "memory")
#define CARRIVE()  asm volatile("bar.arrive %0, %1;" :: "r"(c + 1), "r"(128) : "memory")
#define CSYNC128() asm volatile("bar.sync %0, %1;"   :: "r"(c + 1), "r"(128) : "memory")

        // chain length from prefix mask
        const int kind = mask_kind(maskp);
        int cnt = 0;
#pragma unroll
        for (int k = 0; k < 8; ++k)
            cnt += mask_at(maskp, kind, (jt + 64 * k) * BB + b) ? 1 : 0;
        cnt = __reduce_add_sync(0xffffffffu, cnt);
        if (l == 0) red[c][w] = (float)cnt;
        CBAR();
        const int len = (int)red[c][0] + (int)red[c][1];

        // E column jt, i-pair packed: 32 x f32x2 registers
        ull E[32];
        {
            const ull* ep = (const ull*)(g_EpT + jt * NN);
#pragma unroll
            for (int k = 0; k < 32; ++k) E[k] = ep[k];
        }

        const float* eb = emit + (size_t)b * NN + jt;

        float A = LOG2E * (eb[0] + strans[jt]);
        if (jt == 0) red[c][2] = A;
        CBAR();
        const float M0 = red[c][2];
        float PF = ex2f_(A - M0);
        float mlog = M0;
        float u = 1.0f;

        pbuf[c][1][jt] = PF;
        CARRIVE();
        // prologue shadow: g for step 1, raw ring for steps 2..7
#define LDPF(tt) eb[(size_t)((tt) < TT - 1 ? (tt) : (TT - 1)) * STRIDE_F]
        float gcur = ex2f_(LOG2E * LDPF(1));
        float r0 = LDPF(2), r1 = LDPF(3), r2 = LDPF(4);
        float r3 = LDPF(5), r4 = LDPF(6), r5 = LDPF(7);
        CSYNC128();

        int t = 1;
        // Cadence K = 0..5.  K==4: sample raw sum s into sslot.
        // K==5: read sslot (post-bar of K4), derive scale u, apply, account mlog.
#define BODY(RR, BI, BO, K) {                                                 \
        float gg = gcur;                                                      \
        if (K == 5) {                                                         \
            float v0 = sslot[c];                                              \
            int ex = (int)((__float_as_uint(v0) >> 23) & 0xFF);               \
            int dd = ex - 127;                                                \
            if (ex == 0 || ex == 255) dd = 0;                                 \
            if (dd > 120) dd = 120; if (dd < -120) dd = -120;                 \
            u = __uint_as_float((unsigned)(127 - dd) << 23);                  \
            mlog += (float)dd;                                                \
            gg = gcur * u;                                                    \
        }                                                                     \
        const ulonglong2* pb = (const ulonglong2*)pbuf[c][BI];                \
        ull a0 = 0, a1 = 0, a2 = 0, a3 = 0;                                   \
        _Pragma("unroll")                                                     \
        for (int m = 0; m < 16; m += 2) {                                     \
            ulonglong2 q = pb[m];                                             \
            ulonglong2 r = pb[m + 1];                                         \
            fma2_(a0, q.x, E[2 * m]);     fma2_(a1, q.y, E[2 * m + 1]);       \
            fma2_(a2, r.x, E[2 * m + 2]); fma2_(a3, r.y, E[2 * m + 3]);       \
        }                                                                     \
        float s = pairsum_(add2_(add2_(a0, a1), add2_(a2, a3)));              \
        float pn = s * gg;                                                    \
        pbuf[c][BO][jt] = pn;                                                 \
        if (K == 4 && jt == 0) sslot[c] = s;                                  \
        CARRIVE();                                                            \
        gcur = ex2f_(LOG2E * RR);      /* shadow: inside bar wait window */   \
        RR = LDPF(t + 7);                                                     \
        PF = pn;                                                              \
        ++t;                                                                  \
        CSYNC128(); }

        while (t + 11 < len) {            // ring depth + cadence margin
            BODY(r0, 1, 0, 0)
            BODY(r1, 0, 1, 1)
            BODY(r2, 1, 0, 2)
            BODY(r3, 0, 1, 3)
            BODY(r4, 1, 0, 4)             // sample s
            BODY(r5, 0, 1, 5)             // derive + apply scale
        }
        while (t < len) {                 // ≤11 remainder steps
            float rr = eb[(size_t)t * STRIDE_F];
            int bi = t & 1, bo = bi ^ 1;
            float g = ex2f_(LOG2E * rr);
            const ulonglong2* pb = (const ulonglong2*)pbuf[c][bi];
            ull a0 = 0, a1 = 0, a2 = 0, a3 = 0;
#pragma unroll
            for (int m = 0; m < 16; m += 2) {
                ulonglong2 q = pb[m];
                ulonglong2 r = pb[m + 1];
                fma2_(a0, q.x, E[2 * m]);     fma2_(a1, q.y, E[2 * m + 1]);
                fma2_(a2, r.x, E[2 * m + 2]); fma2_(a3, r.y, E[2 * m + 3]);
            }
            float s = pairsum_(add2_(add2_(a0, a1), add2_(a2, a3)));
            // exact 2^-6-per-step compensation keeps p in fp32 range
            float pn = s * (g * 0.015625f);
            pbuf[c][bo][jt] = pn;
            CBAR();
            mlog += 6.0f;
            PF = pn;
            ++t;
        }

        // logZ_b = ln LSE_j(alpha_j + etrans_j),  alpha(log2) = lg2(PF)+mlog
        float G = lg2f_(PF) + mlog + LOG2E * etrans[jt];
        float m2 = G;
#pragma unroll
        for (int o = 16; o; o >>= 1) m2 = fmaxf(m2, __shfl_xor_sync(0xffffffffu, m2, o));
        float s = ex2f_(G - m2);
#pragma unroll
        for (int o = 16; o; o >>= 1) s += __shfl_xor_sync(0xffffffffu, s, o);
        CBAR();
        if (l == 0) { red[c][w] = m2; red[c][2 + w] = s; }
        CBAR();
        if (jt == 0) {
            float ma = fmaxf(red[c][0], red[c][1]);
            float ss = red[c][2] * ex2f_(red[c][0] - ma)
                     + red[c][3] * ex2f_(red[c][1] - ma);
            atomicAdd(&g_logZ, (double)(LN2F * (ma + lg2f_(ss))));
        }
    } else {
        // ======== gold path score ========
        int idx = (blockIdx.x - FWD_BLOCKS) * 256 + tid;   // = t*BB + b
        int t = idx >> 9;
        int kind = mask_kind(maskp);
        float c = 0.0f;
        if (mask_at(maskp, kind, idx)) {
            int tg = target[idx];
            c = emit[(size_t)idx * NN + tg];
            if (t > 0) c += trans[target[idx - BB] * NN + tg];
            else       c += strans[tg];
            bool mnext = (t < TT - 1) && mask_at(maskp, kind, idx + BB);
            if (!mnext) c += etrans[tg];
        }
#pragma unroll
        for (int o = 16; o; o >>= 1) c += __shfl_xor_sync(0xffffffffu, c, o);
        if ((tid & 31) == 0) atomicAdd(&g_gold, (double)c);
    }

    // ======== last block writes the result ========
    __syncthreads();
    if (tid == 0) {
        __threadfence();
        if (atomicAdd(&g_done, 1u) == TOT_BLOCKS - 1) {
            double lz = atomicAdd(&g_logZ, 0.0);
            double gd = atomicAdd(&g_gold, 0.0);
            out[0] = (float)(lz - gd);
        }
    }
}

extern "C" void kernel_launch(void* const* d_in, const int* in_sizes, int n_in,
                              void* d_out, int out_size) {
    const float* emit   = (const float*)d_in[0];
    const float* trans  = (const float*)d_in[1];
    const float* strans = (const float*)d_in[2];
    const float* etrans = (const float*)d_in[3];
    const int*   target = (const int*)d_in[4];
    const void*  mask   = d_in[5];
    (void)in_sizes; (void)n_in; (void)out_size;

    k_init<<<16, 256>>>(trans);
    k_main<<<TOT_BLOCKS, 256>>>(emit, trans, strans, etrans, target, mask,
                                (float*)d_out);
}

// round 13
// speedup vs baseline: 1.1156x; 1.1156x over previous
#include <cuda_runtime.h>

// CRF loss: logZ - gold.  T=512, B=512, N=64.
// Exp-space forward. 1 chain per 64-thread block (cheap BAR0 sync),
// 4-accumulator matvec, ex2+prefetch in the pre-bar shadow window,
// power-of-2 renorm sampled/applied on 2 of every 6 steps.

#define TT 512
#define BB 512
#define NN 64
#define LOG2E 1.4426950408889634f
#define LN2F  0.6931471805599453f
#define STRIDE_F (BB * NN)

#define FWD_BLOCKS  512                  // one chain per 64-thread block
#define GOLD_BLOCKS 4096                 // (T*B)/64
#define TOT_BLOCKS  (FWD_BLOCKS + GOLD_BLOCKS)

typedef unsigned long long ull;

__device__ __align__(16) float g_EpT[NN * NN];   // exp(trans)^T : [j][i]
__device__ double   g_logZ;
__device__ double   g_gold;
__device__ unsigned g_done;

__device__ __forceinline__ float ex2f_(float x) {
    float y; asm("ex2.approx.ftz.f32 %0, %1;" : "=f"(y) : "f"(x)); return y;
}
__device__ __forceinline__ float lg2f_(float x) {
    float y; asm("lg2.approx.ftz.f32 %0, %1;" : "=f"(y) : "f"(x)); return y;
}
__device__ __forceinline__ void fma2_(ull& d, ull a, ull b) {
    asm("fma.rn.f32x2 %0, %1, %2, %0;" : "+l"(d) : "l"(a), "l"(b));
}
__device__ __forceinline__ ull add2_(ull a, ull b) {
    ull d; asm("add.rn.f32x2 %0, %1, %2;" : "=l"(d) : "l"(a), "l"(b));
    return d;
}
__device__ __forceinline__ float pairsum_(ull a) {
    unsigned lo, hi;
    asm("mov.b64 {%0, %1}, %2;" : "=r"(lo), "=r"(hi) : "l"(a));
    return __uint_as_float(lo) + __uint_as_float(hi);
}

// mask dtype: 0=int32, 1=float32, 2=byte  (row t=0 all-true since lengths>=1)
__device__ __forceinline__ int mask_kind(const void* maskp) {
    unsigned w0 = ((const unsigned*)maskp)[0];
    return (w0 == 1u) ? 0 : (w0 == 0x3F800000u ? 1 : 2);
}
__device__ __forceinline__ bool mask_at(const void* maskp, int kind, int idx) {
    if (kind == 0) return ((const int*)maskp)[idx] != 0;
    if (kind == 1) return ((const float*)maskp)[idx] != 0.0f;
    return ((const unsigned char*)maskp)[idx] != 0;
}

// ---------------- init ------------------------------------------------------
__global__ void k_init(const float* __restrict__ trans) {
    int tid = blockIdx.x * blockDim.x + threadIdx.x;
    if (tid < NN * NN) {
        int i = tid & (NN - 1);
        int j = tid >> 6;
        g_EpT[tid] = ex2f_(LOG2E * trans[i * NN + j]);
    }
    if (tid == 0) { g_logZ = 0.0; g_gold = 0.0; g_done = 0u; }
}

// ---------------- fused forward + gold + final ------------------------------
__global__ void __launch_bounds__(64, 1)
k_main(const float* __restrict__ emit,
       const float* __restrict__ trans,
       const float* __restrict__ strans,
       const float* __restrict__ etrans,
       const int*   __restrict__ target,
       const void*  __restrict__ maskp,
       float*       __restrict__ out) {
    __shared__ __align__(16) float pbuf[2][NN];   // p vector, double-buffered
    __shared__ float sslot;                       // raw-sum sample (j = 0)
    __shared__ float red[4];

    const int tid = threadIdx.x;

    if (blockIdx.x < FWD_BLOCKS) {
        const int w = tid >> 5;
        const int l = tid & 31;
        const int jt = tid;               // lane owns state column jt
        const int b = blockIdx.x;

        // chain length from prefix mask
        const int kind = mask_kind(maskp);
        int cnt = 0;
#pragma unroll
        for (int k = 0; k < 8; ++k)
            cnt += mask_at(maskp, kind, (tid + 64 * k) * BB + b) ? 1 : 0;
        cnt = __reduce_add_sync(0xffffffffu, cnt);
        if (l == 0) red[w] = (float)cnt;
        __syncthreads();
        const int len = (int)red[0] + (int)red[1];

        // E column jt, i-pair packed: 32 x f32x2 registers
        ull E[32];
        {
            const ull* ep = (const ull*)(g_EpT + jt * NN);
#pragma unroll
            for (int k = 0; k < 32; ++k) E[k] = ep[k];
        }

        const float* eb = emit + (size_t)b * NN + jt;

        float A = LOG2E * (eb[0] + strans[jt]);
        if (tid == 0) red[2] = A;
        __syncthreads();
        const float M0 = red[2];
        float PF = ex2f_(A - M0);
        float mlog = M0;
        float u = 1.0f;

        pbuf[1][jt] = PF;

        // prologue shadow: g for step 1, raw ring for steps 2..7
#define LDPF(tt) eb[(size_t)((tt) < TT - 1 ? (tt) : (TT - 1)) * STRIDE_F]
        float gcur = ex2f_(LOG2E * LDPF(1));
        float r0 = LDPF(2), r1 = LDPF(3), r2 = LDPF(4);
        float r3 = LDPF(5), r4 = LDPF(6), r5 = LDPF(7);
        __syncthreads();

        int t = 1;
        // Cadence K = 0..5.  K==4: sample raw sum s into sslot (pre-bar).
        // K==5: read sslot (safe: after K4's bar), derive scale u, apply,
        //       account mlog. Other steps: pn = s * g only.
#define BODY(RR, BI, BO, K) {                                                 \
        float gg = gcur;                                                      \
        if (K == 5) {                                                         \
            float v0 = sslot;                                                 \
            int ex = (int)((__float_as_uint(v0) >> 23) & 0xFF);               \
            int dd = ex - 127;                                                \
            if (ex == 0 || ex == 255) dd = 0;                                 \
            if (dd > 120) dd = 120; if (dd < -120) dd = -120;                 \
            u = __uint_as_float((unsigned)(127 - dd) << 23);                  \
            mlog += (float)dd;                                                \
            gg = gcur * u;                                                    \
        }                                                                     \
        const ulonglong2* pb = (const ulonglong2*)pbuf[BI];                   \
        ull a0 = 0, a1 = 0, a2 = 0, a3 = 0;                                   \
        _Pragma("unroll")                                                     \
        for (int m = 0; m < 16; m += 2) {                                     \
            ulonglong2 q = pb[m];                                             \
            ulonglong2 r = pb[m + 1];                                         \
            fma2_(a0, q.x, E[2 * m]);     fma2_(a1, q.y, E[2 * m + 1]);       \
            fma2_(a2, r.x, E[2 * m + 2]); fma2_(a3, r.y, E[2 * m + 3]);       \
        }                                                                     \
        float s = pairsum_(add2_(add2_(a0, a1), add2_(a2, a3)));              \
        float pn = s * gg;                                                    \
        pbuf[BO][jt] = pn;                                                    \
        if (K == 4 && jt == 0) sslot = s;                                     \
        gcur = ex2f_(LOG2E * RR);      /* shadow work before the bar */       \
        RR = LDPF(t + 7);                                                     \
        PF = pn;                                                              \
        ++t;                                                                  \
        __syncthreads(); }

        while (t + 11 < len) {            // cadence-aligned: t ≡ 1 (mod 6)
            BODY(r0, 1, 0, 0)
            BODY(r1, 0, 1, 1)
            BODY(r2, 1, 0, 2)
            BODY(r3, 0, 1, 3)
            BODY(r4, 1, 0, 4)             // sample s
            BODY(r5, 0, 1, 5)             // derive + apply scale
        }
        while (t < len) {                 // ≤11 remainder steps
            float rr = eb[(size_t)t * STRIDE_F];
            int bi = t & 1, bo = bi ^ 1;
            float g = ex2f_(LOG2E * rr);
            const ulonglong2* pb = (const ulonglong2*)pbuf[bi];
            ull a0 = 0, a1 = 0, a2 = 0, a3 = 0;
#pragma unroll
            for (int m = 0; m < 16; m += 2) {
                ulonglong2 q = pb[m];
                ulonglong2 r = pb[m + 1];
                fma2_(a0, q.x, E[2 * m]);     fma2_(a1, q.y, E[2 * m + 1]);
                fma2_(a2, r.x, E[2 * m + 2]); fma2_(a3, r.y, E[2 * m + 3]);
            }
            float s = pairsum_(add2_(add2_(a0, a1), add2_(a2, a3)));
            // exact 2^-6-per-step compensation keeps p in fp32 range
            float pn = s * (g * 0.015625f);
            pbuf[bo][jt] = pn;
            mlog += 6.0f;
            PF = pn;
            ++t;
            __syncthreads();
        }

        // logZ_b = ln LSE_j(alpha_j + etrans_j),  alpha(log2) = lg2(PF)+mlog
        float G = lg2f_(PF) + mlog + LOG2E * etrans[jt];
        float m2 = G;
#pragma unroll
        for (int o = 16; o; o >>= 1) m2 = fmaxf(m2, __shfl_xor_sync(0xffffffffu, m2, o));
        float s = ex2f_(G - m2);
#pragma unroll
        for (int o = 16; o; o >>= 1) s += __shfl_xor_sync(0xffffffffu, s, o);
        __syncthreads();
        if (l == 0) { red[w] = m2; red[2 + w] = s; }
        __syncthreads();
        if (tid == 0) {
            float ma = fmaxf(red[0], red[1]);
            float ss = red[2] * ex2f_(red[0] - ma) + red[3] * ex2f_(red[1] - ma);
            atomicAdd(&g_logZ, (double)(LN2F * (ma + lg2f_(ss))));
        }
    } else {
        // ======== gold path score ========
        int idx = (blockIdx.x - FWD_BLOCKS) * 64 + tid;   // = t*BB + b
        int t = idx >> 9;
        int kind = mask_kind(maskp);
        float c = 0.0f;
        if (mask_at(maskp, kind, idx)) {
            int tg = target[idx];
            c = emit[(size_t)idx * NN + tg];
            if (t > 0) c += trans[target[idx - BB] * NN + tg];
            else       c += strans[tg];
            bool mnext = (t < TT - 1) && mask_at(maskp, kind, idx + BB);
            if (!mnext) c += etrans[tg];
        }
#pragma unroll
        for (int o = 16; o; o >>= 1) c += __shfl_xor_sync(0xffffffffu, c, o);
        if ((tid & 31) == 0) atomicAdd(&g_gold, (double)c);
    }

    // ======== last block writes the result ========
    __syncthreads();
    if (tid == 0) {
        __threadfence();
        if (atomicAdd(&g_done, 1u) == TOT_BLOCKS - 1) {
            double lz = atomicAdd(&g_logZ, 0.0);
            double gd = atomicAdd(&g_gold, 0.0);
            out[0] = (float)(lz - gd);
        }
    }
}

extern "C" void kernel_launch(void* const* d_in, const int* in_sizes, int n_in,
                              void* d_out, int out_size) {
    const float* emit   = (const float*)d_in[0];
    const float* trans  = (const float*)d_in[1];
    const float* strans = (const float*)d_in[2];
    const float* etrans = (const float*)d_in[3];
    const int*   target = (const int*)d_in[4];
    const void*  mask   = d_in[5];
    (void)in_sizes; (void)n_in; (void)out_size;

    k_init<<<16, 256>>>(trans);
    k_main<<<TOT_BLOCKS, 64>>>(emit, trans, strans, etrans, target, mask,
                               (float*)d_out);
}

// round 14
// speedup vs baseline: 1.1453x; 1.0266x over previous
#include <cuda_runtime.h>

// CRF loss: logZ - gold.  T=512, B=512, N=64.
// Exp-space forward. 1 chain per 64-thread block, 4-accumulator matvec,
// ex2+pointer-strided prefetch in the pre-bar shadow window,
// power-of-2 renorm sampled/applied on 2 of every 6 steps.

#define TT 512
#define BB 512
#define NN 64
#define LOG2E 1.4426950408889634f
#define LN2F  0.6931471805599453f
#define STRIDE_F (BB * NN)

#define FWD_BLOCKS  512                  // one chain per 64-thread block
#define GOLD_BLOCKS 4096                 // (T*B)/64
#define TOT_BLOCKS  (FWD_BLOCKS + GOLD_BLOCKS)

typedef unsigned long long ull;

__device__ __align__(16) float g_EpT[NN * NN];   // exp(trans)^T : [j][i]
__device__ double   g_logZ;
__device__ double   g_gold;
__device__ unsigned g_done;

__device__ __forceinline__ float ex2f_(float x) {
    float y; asm("ex2.approx.ftz.f32 %0, %1;" : "=f"(y) : "f"(x)); return y;
}
__device__ __forceinline__ float lg2f_(float x) {
    float y; asm("lg2.approx.ftz.f32 %0, %1;" : "=f"(y) : "f"(x)); return y;
}
__device__ __forceinline__ void fma2_(ull& d, ull a, ull b) {
    asm("fma.rn.f32x2 %0, %1, %2, %0;" : "+l"(d) : "l"(a), "l"(b));
}
__device__ __forceinline__ ull add2_(ull a, ull b) {
    ull d; asm("add.rn.f32x2 %0, %1, %2;" : "=l"(d) : "l"(a), "l"(b));
    return d;
}
__device__ __forceinline__ float pairsum_(ull a) {
    unsigned lo, hi;
    asm("mov.b64 {%0, %1}, %2;" : "=r"(lo), "=r"(hi) : "l"(a));
    return __uint_as_float(lo) + __uint_as_float(hi);
}

// mask dtype: 0=int32, 1=float32, 2=byte  (row t=0 all-true since lengths>=1)
__device__ __forceinline__ int mask_kind(const void* maskp) {
    unsigned w0 = ((const unsigned*)maskp)[0];
    return (w0 == 1u) ? 0 : (w0 == 0x3F800000u ? 1 : 2);
}
__device__ __forceinline__ bool mask_at(const void* maskp, int kind, int idx) {
    if (kind == 0) return ((const int*)maskp)[idx] != 0;
    if (kind == 1) return ((const float*)maskp)[idx] != 0.0f;
    return ((const unsigned char*)maskp)[idx] != 0;
}

// ---------------- init ------------------------------------------------------
__global__ void k_init(const float* __restrict__ trans) {
    int tid = blockIdx.x * blockDim.x + threadIdx.x;
    if (tid < NN * NN) {
        int i = tid & (NN - 1);
        int j = tid >> 6;
        g_EpT[tid] = ex2f_(LOG2E * trans[i * NN + j]);
    }
    if (tid == 0) { g_logZ = 0.0; g_gold = 0.0; g_done = 0u; }
}

// ---------------- fused forward + gold + final ------------------------------
__global__ void __launch_bounds__(64, 1)
k_main(const float* __restrict__ emit,
       const float* __restrict__ trans,
       const float* __restrict__ strans,
       const float* __restrict__ etrans,
       const int*   __restrict__ target,
       const void*  __restrict__ maskp,
       float*       __restrict__ out) {
    __shared__ __align__(16) float pbuf[2][NN];   // p vector, double-buffered
    __shared__ float sslot;                       // raw-sum sample (j = 0)
    __shared__ float red[4];

    const int tid = threadIdx.x;

    if (blockIdx.x < FWD_BLOCKS) {
        const int w = tid >> 5;
        const int l = tid & 31;
        const int jt = tid;               // lane owns state column jt
        const int b = blockIdx.x;

        // chain length from prefix mask
        const int kind = mask_kind(maskp);
        int cnt = 0;
#pragma unroll
        for (int k = 0; k < 8; ++k)
            cnt += mask_at(maskp, kind, (tid + 64 * k) * BB + b) ? 1 : 0;
        cnt = __reduce_add_sync(0xffffffffu, cnt);
        if (l == 0) red[w] = (float)cnt;
        __syncthreads();
        const int len = (int)red[0] + (int)red[1];

        // E column jt, i-pair packed: 32 x f32x2 registers
        ull E[32];
        {
            const ull* ep = (const ull*)(g_EpT + jt * NN);
#pragma unroll
            for (int k = 0; k < 32; ++k) E[k] = ep[k];
        }

        const float* eb = emit + (size_t)b * NN + jt;

        float A = LOG2E * (eb[0] + strans[jt]);
        if (tid == 0) red[2] = A;
        __syncthreads();
        const float M0 = red[2];
        float PF = ex2f_(A - M0);
        float mlog = M0;
        float u = 1.0f;

        pbuf[1][jt] = PF;

        // prologue shadow: g for step 1, raw ring for steps 2..7 (clamped)
#define LDPF(tt) eb[(size_t)((tt) < TT - 1 ? (tt) : (TT - 1)) * STRIDE_F]
        float gcur = ex2f_(LOG2E * LDPF(1));
        float r0 = LDPF(2), r1 = LDPF(3), r2 = LDPF(4);
        float r3 = LDPF(5), r4 = LDPF(6), r5 = LDPF(7);
        // steady-loop prefetch pointer: next load is row t+7 = 8
        const float* pf = eb + (size_t)8 * STRIDE_F;
        __syncthreads();

        int t = 1;
        // Cadence K = 0..5.  K==4: sample raw sum s into sslot (pre-bar).
        // K==5: read sslot (safe: after K4's bar), derive scale u, apply,
        //       account mlog. Other steps: pn = s * g only.
        // Guard t+12<len ensures every *pf deref (row t+7 <= t0+12 < len <= TT)
        // is in range, so no clamp / min in the steady loop.
#define BODY(RR, BI, BO, K) {                                                 \
        float gg = gcur;                                                      \
        if (K == 5) {                                                         \
            float v0 = sslot;                                                 \
            int ex = (int)((__float_as_uint(v0) >> 23) & 0xFF);               \
            int dd = ex - 127;                                                \
            if (ex == 0 || ex == 255) dd = 0;                                 \
            if (dd > 120) dd = 120; if (dd < -120) dd = -120;                 \
            u = __uint_as_float((unsigned)(127 - dd) << 23);                  \
            mlog += (float)dd;                                                \
            gg = gcur * u;                                                    \
        }                                                                     \
        const ulonglong2* pb = (const ulonglong2*)pbuf[BI];                   \
        ull a0 = 0, a1 = 0, a2 = 0, a3 = 0;                                   \
        _Pragma("unroll")                                                     \
        for (int m = 0; m < 16; m += 2) {                                     \
            ulonglong2 q = pb[m];                                             \
            ulonglong2 r = pb[m + 1];                                         \
            fma2_(a0, q.x, E[2 * m]);     fma2_(a1, q.y, E[2 * m + 1]);       \
            fma2_(a2, r.x, E[2 * m + 2]); fma2_(a3, r.y, E[2 * m + 3]);       \
        }                                                                     \
        float s = pairsum_(add2_(add2_(a0, a1), add2_(a2, a3)));              \
        float pn = s * gg;                                                    \
        pbuf[BO][jt] = pn;                                                    \
        if (K == 4 && jt == 0) sslot = s;                                     \
        gcur = ex2f_(LOG2E * RR);      /* shadow work before the bar */       \
        RR = *pf; pf += STRIDE_F;      /* clamp-free strided prefetch */      \
        PF = pn;                                                              \
        ++t;                                                                  \
        __syncthreads(); }

        while (t + 12 < len) {            // cadence-aligned: t ≡ 1 (mod 6)
            BODY(r0, 1, 0, 0)
            BODY(r1, 0, 1, 1)
            BODY(r2, 1, 0, 2)
            BODY(r3, 0, 1, 3)
            BODY(r4, 1, 0, 4)             // sample s
            BODY(r5, 0, 1, 5)             // derive + apply scale
        }
        {
            const float* er = eb + (size_t)t * STRIDE_F;
            while (t < len) {             // ≤12 remainder steps
                float rr = *er; er += STRIDE_F;
                int bi = t & 1, bo = bi ^ 1;
                float g = ex2f_(LOG2E * rr);
                const ulonglong2* pb = (const ulonglong2*)pbuf[bi];
                ull a0 = 0, a1 = 0, a2 = 0, a3 = 0;
#pragma unroll
                for (int m = 0; m < 16; m += 2) {
                    ulonglong2 q = pb[m];
                    ulonglong2 r = pb[m + 1];
                    fma2_(a0, q.x, E[2 * m]);     fma2_(a1, q.y, E[2 * m + 1]);
                    fma2_(a2, r.x, E[2 * m + 2]); fma2_(a3, r.y, E[2 * m + 3]);
                }
                float s = pairsum_(add2_(add2_(a0, a1), add2_(a2, a3)));
                // exact 2^-6-per-step compensation keeps p in fp32 range
                float pn = s * (g * 0.015625f);
                pbuf[bo][jt] = pn;
                mlog += 6.0f;
                PF = pn;
                ++t;
                __syncthreads();
            }
        }

        // logZ_b = ln LSE_j(alpha_j + etrans_j),  alpha(log2) = lg2(PF)+mlog
        float G = lg2f_(PF) + mlog + LOG2E * etrans[jt];
        float m2 = G;
#pragma unroll
        for (int o = 16; o; o >>= 1) m2 = fmaxf(m2, __shfl_xor_sync(0xffffffffu, m2, o));
        float s = ex2f_(G - m2);
#pragma unroll
        for (int o = 16; o; o >>= 1) s += __shfl_xor_sync(0xffffffffu, s, o);
        __syncthreads();
        if (l == 0) { red[w] = m2; red[2 + w] = s; }
        __syncthreads();
        if (tid == 0) {
            float ma = fmaxf(red[0], red[1]);
            float ss = red[2] * ex2f_(red[0] - ma) + red[3] * ex2f_(red[1] - ma);
            atomicAdd(&g_logZ, (double)(LN2F * (ma + lg2f_(ss))));
        }
    } else {
        // ======== gold path score ========
        int idx = (blockIdx.x - FWD_BLOCKS) * 64 + tid;   // = t*BB + b
        int t = idx >> 9;
        int kind = mask_kind(maskp);
        float c = 0.0f;
        if (mask_at(maskp, kind, idx)) {
            int tg = target[idx];
            c = emit[(size_t)idx * NN + tg];
            if (t > 0) c += trans[target[idx - BB] * NN + tg];
            else       c += strans[tg];
            bool mnext = (t < TT - 1) && mask_at(maskp, kind, idx + BB);
            if (!mnext) c += etrans[tg];
        }
#pragma unroll
        for (int o = 16; o; o >>= 1) c += __shfl_xor_sync(0xffffffffu, c, o);
        if ((tid & 31) == 0) atomicAdd(&g_gold, (double)c);
    }

    // ======== last block writes the result ========
    __syncthreads();
    if (tid == 0) {
        __threadfence();
        if (atomicAdd(&g_done, 1u) == TOT_BLOCKS - 1) {
            double lz = atomicAdd(&g_logZ, 0.0);
            double gd = atomicAdd(&g_gold, 0.0);
            out[0] = (float)(lz - gd);
        }
    }
}

extern "C" void kernel_launch(void* const* d_in, const int* in_sizes, int n_in,
                              void* d_out, int out_size) {
    const float* emit   = (const float*)d_in[0];
    const float* trans  = (const float*)d_in[1];
    const float* strans = (const float*)d_in[2];
    const float* etrans = (const float*)d_in[3];
    const int*   target = (const int*)d_in[4];
    const void*  mask   = d_in[5];
    (void)in_sizes; (void)n_in; (void)out_size;

    k_init<<<16, 256>>>(trans);
    k_main<<<TOT_BLOCKS, 64>>>(emit, trans, strans, etrans, target, mask,
                               (float*)d_out);
}